// round 15
// baseline (speedup 1.0000x reference)
#include <cuda_runtime.h>
#include <cstdint>

// EdgeEmbedding: out[i, :] = edge_type_embedding[data[i], :] + type_attr_sum[data[i], :]
//
// R12 design (unbenched R13/R14, broker timeouts; resubmitting with one
// barrier hardening): all three phases fused into ONE kernel with software
// grid barriers (R3/R12 evidence: STG vs bulk-DMA gather identical to the
// microsecond -> gather is HBM-write-bound; remaining slack is the ~14us
// prologue of two small kernels + launch gaps).
//
//   Step A: comb[t,:] = ete[t,:]                    (cooperative copy)
//   --- grid barrier ---
//   Step B: comb[seg[a],:] += attr_table[id[a],:]   (atomic segment sum)
//   --- grid barrier ---
//   Step C: smem slice load + per-edge 1KB bulk-DMA row stores
//
// R14 hardening: the pre-arrive generation snapshot is now an atomic RMW
// (atomicAdd(&gen,0)) instead of a volatile load, so it cannot be reordered
// relative to the arrive atomicAdd. Prevents a rare early-fallthrough where
// a waiter snapshots a post-release gen and skips the wait.
//
// Co-residency: 145 CTAs x 512 thr x 200KB smem -> 1 CTA/SM on 148 SMs, all
// resident in wave 1, so the spin barrier cannot deadlock. Generation counter
// is monotone (never reset) -> safe across CUDA-graph replays.

#define NUM_TYPES 1000
#define DIM 256
#define DIM4 (DIM / 4)          // 64 float4 per row
#define ROW_BYTES 1024

#define TYPES_PER_SLICE 200
#define NUM_SLICES 5            // 5 * 200 = 1000
#define BLOCKS_PER_SLICE 29     // 5 * 29 = 145 CTAs
#define NCTAS (NUM_SLICES * BLOCKS_PER_SLICE)
#define THREADS 512
#define GTHREADS (NCTAS * THREADS)
#define SLICE_SMEM_BYTES (TYPES_PER_SLICE * DIM * sizeof(float))  // 204800

__device__ float g_comb[NUM_TYPES * DIM];
__device__ unsigned g_bar_count = 0;
__device__ unsigned g_bar_gen   = 0;

// ---------------------------------------------------------------------------
// Grid barrier: generation-counter based, replay-safe (gen never resets).
// ---------------------------------------------------------------------------
__device__ __forceinline__ void grid_barrier() {
    __syncthreads();
    if (threadIdx.x == 0) {
        __threadfence();                                   // publish my writes
        unsigned my_gen = atomicAdd(&g_bar_gen, 0);        // ordered snapshot BEFORE arrive
        unsigned pos = atomicAdd(&g_bar_count, 1);
        if (pos == NCTAS - 1) {
            atomicExch(&g_bar_count, 0);                   // reset for next barrier
            __threadfence();
            atomicAdd(&g_bar_gen, 1);                      // release waiters
        } else {
            while (atomicAdd(&g_bar_gen, 0) == my_gen) { __nanosleep(64); }
        }
        __threadfence();                                   // acquire others' writes
    }
    __syncthreads();
}

// ---------------------------------------------------------------------------
// cp.async.bulk helpers (smem -> global, per-thread bulk-group)
// ---------------------------------------------------------------------------
__device__ __forceinline__ void bulk_store_row(void* gdst, uint32_t ssrc) {
    asm volatile(
        "cp.async.bulk.global.shared::cta.bulk_group [%0], [%1], %2;"
        :: "l"(gdst), "r"(ssrc), "n"(ROW_BYTES) : "memory");
}
__device__ __forceinline__ void bulk_commit() {
    asm volatile("cp.async.bulk.commit_group;" ::: "memory");
}
template <int N>
__device__ __forceinline__ void bulk_wait() {
    asm volatile("cp.async.bulk.wait_group %0;" :: "n"(N) : "memory");
}

// ---------------------------------------------------------------------------
// Fused kernel
// ---------------------------------------------------------------------------
__global__ void __launch_bounds__(THREADS, 1)
fused_edge_embedding_kernel(const int*   __restrict__ data,
                            const float* __restrict__ attr_table,
                            const float* __restrict__ ete,
                            const int*   __restrict__ flat_attr_ids,
                            const int*   __restrict__ attr_seg_ids,
                            float*       __restrict__ out,
                            int n, int total_attrs) {
    extern __shared__ float4 s_comb[];   // TYPES_PER_SLICE * 64 float4
    int gtid = blockIdx.x * THREADS + threadIdx.x;

    // ---- Step A: comb = ete (1 MB copy; 16000 float4) -----------------
    {
        const float4* src = reinterpret_cast<const float4*>(ete);
        float4* dst = reinterpret_cast<float4*>(g_comb);
        for (int i = gtid; i < NUM_TYPES * DIM4; i += GTHREADS)
            dst[i] = src[i];
    }
    grid_barrier();

    // ---- Step B: atomic segment sum ------------------------------------
    {
        int total = total_attrs * DIM4;
        for (int w = gtid; w < total; w += GTHREADS) {
            int a = w >> 6;            // attr index
            int c = w & (DIM4 - 1);    // float4 chunk within row
            int id  = flat_attr_ids[a];
            int seg = attr_seg_ids[a];
            float4 v = reinterpret_cast<const float4*>(attr_table)[(long long)id * DIM4 + c];
            float* dst = &g_comb[seg * DIM + c * 4];
            atomicAdd(dst + 0, v.x);
            atomicAdd(dst + 1, v.y);
            atomicAdd(dst + 2, v.z);
            atomicAdd(dst + 3, v.w);
        }
    }
    grid_barrier();

    // ---- Step C: smem-sliced gather with DMA row stores -----------------
    int slice = blockIdx.x / BLOCKS_PER_SLICE;
    int b     = blockIdx.x % BLOCKS_PER_SLICE;
    int t_lo  = slice * TYPES_PER_SLICE;
    int t_hi  = t_lo + TYPES_PER_SLICE;
    if (t_hi > NUM_TYPES) t_hi = NUM_TYPES;
    int nt = t_hi - t_lo;

    const float4* comb4 = reinterpret_cast<const float4*>(g_comb);
    for (int i = threadIdx.x; i < nt * DIM4; i += THREADS)
        s_comb[i] = comb4[t_lo * DIM4 + i];
    __syncthreads();

    uint32_t s_base;
    asm("{ .reg .u64 t; cvta.to.shared.u64 t, %1; cvt.u32.u64 %0, t; }"
        : "=r"(s_base) : "l"((const void*)s_comb));

    int chunk = (n + BLOCKS_PER_SLICE - 1) / BLOCKS_PER_SLICE;
    int e0 = b * chunk;
    int e1 = e0 + chunk;
    if (e1 > n) e1 = n;

    for (int e = e0 + threadIdx.x; e < e1; e += THREADS) {
        int t = __ldg(&data[e]);
        if (t >= t_lo && t < t_hi) {
            uint32_t src = s_base + (uint32_t)(t - t_lo) * ROW_BYTES;
            void* dst = (void*)(out + (long long)e * DIM);
            bulk_store_row(dst, src);
        }
        bulk_commit();
        bulk_wait<6>();   // bound in-flight DMA (~6 KB/thread)
    }
    // Drain before CTA (and its smem) retires.
    bulk_commit();
    bulk_wait<0>();
}

// ---------------------------------------------------------------------------
// Launch. Inputs (metadata order):
//   d_in[0] data              [N]           int32
//   d_in[1] attr_table        [200000*256]  float32
//   d_in[2] edge_type_embed   [1000*256]    float32
//   d_in[3] flat_attr_ids     [50000]       int32
//   d_in[4] attr_seg_ids      [50000]       int32
// out: [N*256] float32
// ---------------------------------------------------------------------------
extern "C" void kernel_launch(void* const* d_in, const int* in_sizes, int n_in,
                              void* d_out, int out_size) {
    const int*   data        = (const int*)d_in[0];
    const float* attr_table  = (const float*)d_in[1];
    const float* ete         = (const float*)d_in[2];
    const int*   flat_ids    = (const int*)d_in[3];
    const int*   seg_ids     = (const int*)d_in[4];
    float*       out         = (float*)d_out;

    int n           = in_sizes[0];
    int total_attrs = in_sizes[3];

    static bool attr_set = false;
    if (!attr_set) {
        cudaFuncSetAttribute(fused_edge_embedding_kernel,
                             cudaFuncAttributeMaxDynamicSharedMemorySize,
                             SLICE_SMEM_BYTES);
        attr_set = true;
    }

    fused_edge_embedding_kernel<<<NCTAS, THREADS, SLICE_SMEM_BYTES>>>(
        data, attr_table, ete, flat_ids, seg_ids, out, n, total_attrs);
}